// round 6
// baseline (speedup 1.0000x reference)
#include <cuda_runtime.h>
#include <cuda_fp16.h>
#include <math.h>
#include <float.h>
#include <stdint.h>

#define N_ROWS   8192
#define C_DIM    256
#define K_CODES  16384
#define OUT_EMB  2097152

// ---------------- scratch (static, no allocations) ----------------
__device__ __align__(16) __half g_zhi[N_ROWS * C_DIM];
__device__ __align__(16) __half g_zlo[N_ROWS * C_DIM];
__device__ __align__(16) __half g_ehi[K_CODES * C_DIM];
__device__ __align__(16) __half g_elo[K_CODES * C_DIM];
__device__ __align__(16) float g_enorm[K_CODES];
__device__ unsigned long long g_best[N_ROWS];
__device__ int    g_idx[N_ROWS];
__device__ int    g_hist[K_CODES];
__device__ double g_accum;

// ---------------- PTX helpers (compute_100-legal) ----------------
__device__ __forceinline__ uint32_t smem_u32(const void* p) {
    uint32_t a;
    asm("{ .reg .u64 t; cvta.to.shared.u64 t, %1; cvt.u32.u64 %0, t; }"
        : "=r"(a) : "l"(p));
    return a;
}
__device__ __forceinline__ void cp_async16(uint32_t saddr, const void* gaddr) {
    asm volatile("cp.async.cg.shared.global [%0], [%1], 16;\n"
                 :: "r"(saddr), "l"(gaddr));
}
__device__ __forceinline__ void cp_commit() {
    asm volatile("cp.async.commit_group;\n");
}
template <int N>
__device__ __forceinline__ void cp_wait() {
    asm volatile("cp.async.wait_group %0;\n" :: "n"(N));
}
__device__ __forceinline__ void ldsm4(uint32_t* r, uint32_t addr) {
    asm volatile("ldmatrix.sync.aligned.m8n8.x4.shared.b16 {%0,%1,%2,%3}, [%4];"
                 : "=r"(r[0]), "=r"(r[1]), "=r"(r[2]), "=r"(r[3]) : "r"(addr));
}
__device__ __forceinline__ void mma_f16(float* d, const uint32_t* a,
                                        uint32_t b0, uint32_t b1) {
    asm volatile(
        "mma.sync.aligned.m16n8k16.row.col.f32.f16.f16.f32 "
        "{%0,%1,%2,%3}, {%4,%5,%6,%7}, {%8,%9}, {%0,%1,%2,%3};"
        : "+f"(d[0]), "+f"(d[1]), "+f"(d[2]), "+f"(d[3])
        : "r"(a[0]), "r"(a[1]), "r"(a[2]), "r"(a[3]), "r"(b0), "r"(b1));
}

// ---------------- init ----------------
__global__ void init_kernel() {
    int t = blockIdx.x * blockDim.x + threadIdx.x;
    if (t < K_CODES) g_hist[t] = 0;
    if (t < N_ROWS) g_best[t] = 0xFFFFFFFFFFFFFFFFull;
    if (t == 0) g_accum = 0.0;
}

// ---------------- z [B,C,T,H,W] -> zhi/zlo [N, C] (fp16 split) ------
__global__ void split_z(const float* __restrict__ z) {
    __shared__ float s[32][33];
    int n0 = blockIdx.x * 32, c0 = blockIdx.y * 32;
    int tx = threadIdx.x, ty = threadIdx.y;
#pragma unroll
    for (int k = 0; k < 4; k++) {
        int yy = ty + k * 8;
        int c = c0 + yy;
        int n = n0 + tx;
        int b = n >> 11, thw = n & 2047;
        s[yy][tx] = z[((b * C_DIM + c) << 11) + thw];
    }
    __syncthreads();
#pragma unroll
    for (int k = 0; k < 4; k++) {
        int yy = ty + k * 8;
        float v = s[tx][yy];
        __half hi = __float2half_rn(v);
        float lo = v - __half2float(hi);
        int o = (n0 + yy) * C_DIM + c0 + tx;
        g_zhi[o] = hi;
        g_zlo[o] = __float2half_rn(lo);
    }
}

// ---------------- emb -> ehi/elo (fp16 split) + ||e||^2 -------------
__global__ void split_e(const float* __restrict__ emb) {
    int w = (blockIdx.x * blockDim.x + threadIdx.x) >> 5;
    int lane = threadIdx.x & 31;
    if (w >= K_CODES) return;
    const float4* e4 = (const float4*)(emb + (size_t)w * C_DIM);
    __half2* h2 = (__half2*)(g_ehi + (size_t)w * C_DIM);
    __half2* l2 = (__half2*)(g_elo + (size_t)w * C_DIM);
    float s = 0.f;
#pragma unroll
    for (int q = 0; q < 2; q++) {
        float4 v = e4[q * 32 + lane];
        s += v.x * v.x + v.y * v.y + v.z * v.z + v.w * v.w;
        __half hx = __float2half_rn(v.x), hy = __float2half_rn(v.y);
        __half hz = __float2half_rn(v.z), hw = __float2half_rn(v.w);
        __half lx = __float2half_rn(v.x - __half2float(hx));
        __half ly = __float2half_rn(v.y - __half2float(hy));
        __half lz = __float2half_rn(v.z - __half2float(hz));
        __half lw = __float2half_rn(v.w - __half2float(hw));
        h2[(q * 32 + lane) * 2 + 0] = __halves2half2(hx, hy);
        h2[(q * 32 + lane) * 2 + 1] = __halves2half2(hz, hw);
        l2[(q * 32 + lane) * 2 + 0] = __halves2half2(lx, ly);
        l2[(q * 32 + lane) * 2 + 1] = __halves2half2(lz, lw);
    }
#pragma unroll
    for (int o = 16; o > 0; o >>= 1) s += __shfl_down_sync(0xffffffffu, s, o);
    if (lane == 0) g_enorm[w] = s;
}

// ---------------- fused 3xFP16 mma.sync GEMM + argmin ---------------
// CTA tile 128(M) x 128(N); 8 warps 2(M) x 4(N); warp tile 64x32.
// K in 8 chunks of 32; 3-stage cp.async ring; 2 CTAs per SM.
// stage: Ahi 8K | Alo 8K | Bhi 8K | Blo 8K = 32K; x3 = 96K + ctrl.
#define STAGE_BYTES 32768
#define CTRL_OFF    98304
#define SMEM_TOTAL  (98304 + 512 + 2048 + 2048)

__global__ void __launch_bounds__(256, 2)
vq_gemm() {
    extern __shared__ __align__(1024) char smem[];
    const uint32_t sb = smem_u32(smem);
    const int tid = threadIdx.x;
    const int wid = tid >> 5, l = tid & 31;
    const int warpM = wid >> 2, warpN = wid & 3;
    const int m0 = blockIdx.x << 7;
    const int n0 = blockIdx.y << 7;

    float* enorm_s = (float*)(smem + CTRL_OFF);            // 512 B
    float* rv = (float*)(smem + CTRL_OFF + 512);           // 2048 B
    int*   ri = (int*)(smem + CTRL_OFF + 2560);            // 2048 B

    if (tid < 128) enorm_s[tid] = g_enorm[n0 + tid];

    // ldmatrix lane addressing: lanes 0-15 -> tile rows 0-15 (k0-7 seg),
    // lanes 16-31 -> same rows, next 16B seg (k8-15).
    uint32_t aoff[4], boff[2];
    int a3[4], b3[2];
#pragma unroll
    for (int mt = 0; mt < 4; mt++) {
        int row = warpM * 64 + mt * 16 + (l & 15);
        aoff[mt] = (uint32_t)(row * 64);
        a3[mt] = row & 3;
    }
#pragma unroll
    for (int ntp = 0; ntp < 2; ntp++) {
        int row = warpN * 32 + ntp * 16 + (l & 15);
        boff[ntp] = (uint32_t)(row * 64);
        b3[ntp] = row & 3;
    }
    const int seghalf = l >> 4;

    // ---- chunk loader: k [32c, 32c+32) -> stage ring slot ----
    auto load_chunk = [&](int c, int stage) {
        const uint32_t base = sb + stage * STAGE_BYTES;
        const int k0 = c * 32;
#pragma unroll
        for (int q = 0; q < 2; q++) {        // A: 128 rows x 64 B per array
            int idx = q * 256 + tid;
            int row = idx >> 2, seg = idx & 3;
            uint32_t so = (uint32_t)(row * 64 + ((seg ^ (row & 3)) << 4));
            size_t go = (size_t)(m0 + row) * C_DIM + k0 + seg * 8;
            cp_async16(base + so,        g_zhi + go);
            cp_async16(base + 8192 + so, g_zlo + go);
        }
#pragma unroll
        for (int q = 0; q < 2; q++) {        // B: 128 rows x 64 B per array
            int idx = q * 256 + tid;
            int row = idx >> 2, seg = idx & 3;
            uint32_t so = (uint32_t)(row * 64 + ((seg ^ (row & 3)) << 4));
            size_t go = (size_t)(n0 + row) * C_DIM + k0 + seg * 8;
            cp_async16(base + 16384 + so, g_ehi + go);
            cp_async16(base + 24576 + so, g_elo + go);
        }
        cp_commit();
    };

    float acc[4][4][4];
#pragma unroll
    for (int mt = 0; mt < 4; mt++)
#pragma unroll
        for (int nt = 0; nt < 4; nt++)
#pragma unroll
            for (int r = 0; r < 4; r++) acc[mt][nt][r] = 0.f;

    load_chunk(0, 0);
    load_chunk(1, 1);

    for (int t = 0; t < 8; t++) {
        if (t < 7) cp_wait<1>(); else cp_wait<0>();
        __syncthreads();                       // all warps done with chunk t-1
        if (t < 6) load_chunk(t + 2, (t + 2) % 3);
        const uint32_t base = sb + (t % 3) * STAGE_BYTES;

#pragma unroll
        for (int ks = 0; ks < 2; ks++) {       // two k16 steps per chunk32
            const int seg = 2 * ks + seghalf;
            uint32_t Ah[4][4], Al[4][4];
#pragma unroll
            for (int mt = 0; mt < 4; mt++) {
                uint32_t ad = base + aoff[mt] +
                              (uint32_t)((seg ^ a3[mt]) << 4);
                ldsm4(Ah[mt], ad);
                ldsm4(Al[mt], ad + 8192);
            }
#pragma unroll
            for (int ntp = 0; ntp < 2; ntp++) {
                uint32_t Bh[4], Bl[4];
                uint32_t bd = base + 16384 + boff[ntp] +
                              (uint32_t)((seg ^ b3[ntp]) << 4);
                ldsm4(Bh, bd);
                ldsm4(Bl, bd + 8192);
#pragma unroll
                for (int sub = 0; sub < 2; sub++) {
                    int nt = ntp * 2 + sub;
#pragma unroll
                    for (int mt = 0; mt < 4; mt++) {
                        mma_f16(acc[mt][nt], Ah[mt], Bh[sub], Bh[sub + 2]);
                        mma_f16(acc[mt][nt], Ah[mt], Bl[sub], Bl[sub + 2]);
                        mma_f16(acc[mt][nt], Al[mt], Bh[sub], Bh[sub + 2]);
                    }
                }
            }
        }
    }

    // ---- epilogue: distances + per-row argmin ----
#pragma unroll
    for (int s = 0; s < 8; s++) {
        const int mt = s >> 1, half = s & 1;
        const int rloc = warpM * 64 + mt * 16 + half * 8 + (l >> 2);
        float bv = INFINITY;
        int bi = 0;
#pragma unroll
        for (int nt = 0; nt < 4; nt++)
#pragma unroll
            for (int j = 0; j < 2; j++) {
                int cl = warpN * 32 + (nt >> 1) * 16 + (nt & 1) * 8 +
                         2 * (l & 3) + j;
                float d = enorm_s[cl] - 2.0f * acc[mt][nt][half * 2 + j];
                if (d < bv) { bv = d; bi = n0 + cl; }
            }
#pragma unroll
        for (int off = 1; off <= 2; off <<= 1) {
            float ov = __shfl_xor_sync(0xffffffffu, bv, off);
            int   oi = __shfl_xor_sync(0xffffffffu, bi, off);
            if (ov < bv || (ov == bv && oi < bi)) { bv = ov; bi = oi; }
        }
        if ((l & 3) == 0) {
            rv[warpN * 128 + rloc] = bv;
            ri[warpN * 128 + rloc] = bi;
        }
    }
    __syncthreads();
    if (tid < 128) {
        float bv = rv[tid];
        int bi = ri[tid];
#pragma unroll
        for (int w = 1; w < 4; w++) {
            float v = rv[w * 128 + tid];
            int i2 = ri[w * 128 + tid];
            if (v < bv || (v == bv && i2 < bi)) { bv = v; bi = i2; }
        }
        unsigned u = __float_as_uint(bv);
        u = (u & 0x80000000u) ? ~u : (u | 0x80000000u);
        unsigned long long key = ((unsigned long long)u << 32) | (unsigned)bi;
        atomicMin(&g_best[m0 + tid], key);
    }
}

// ---------------- merge best -> idx + histogram ----------------
__global__ void merge_kernel() {
    int n = blockIdx.x * blockDim.x + threadIdx.x;
    if (n >= N_ROWS) return;
    int idx = (int)(g_best[n] & 0xFFFFFFFFull);
    g_idx[n] = idx;
    atomicAdd(&g_hist[idx], 1);
}

// ---------------- gather + channels-first output + loss ----------
__global__ void out_kernel(const float* __restrict__ z,
                           const float* __restrict__ emb,
                           float* __restrict__ out) {
    int i = blockIdx.x * blockDim.x + threadIdx.x;
    int b = i >> 19;
    int rem = i & 524287;
    int c = rem >> 11;
    int thw = rem & 2047;
    int n = (b << 11) | thw;
    int idx = g_idx[n];
    float e = emb[(size_t)idx * C_DIM + c];
    out[i] = e;
    if (c == 0) out[OUT_EMB + n] = (float)idx;
    float d = z[i] - e;
    float ss = d * d;
#pragma unroll
    for (int o = 16; o > 0; o >>= 1) ss += __shfl_down_sync(0xffffffffu, ss, o);
    __shared__ float ws[8];
    int lane = threadIdx.x & 31, warp = threadIdx.x >> 5;
    if (lane == 0) ws[warp] = ss;
    __syncthreads();
    if (threadIdx.x < 8) {
        float v = ws[threadIdx.x];
#pragma unroll
        for (int o = 4; o > 0; o >>= 1) v += __shfl_down_sync(0xffu, v, o);
        if (threadIdx.x == 0) atomicAdd(&g_accum, (double)v);
    }
}

// ---------------- perplexity + loss finalize ----------------
__global__ void final_kernel(float* __restrict__ out) {
    __shared__ float ws[8];
    int tid = threadIdx.x;
    float s = 0.f;
    for (int k = tid; k < K_CODES; k += 256) {
        float p = (float)g_hist[k] * (1.0f / N_ROWS);
        s += p * logf(p + 1e-10f);
    }
#pragma unroll
    for (int o = 16; o > 0; o >>= 1) s += __shfl_down_sync(0xffffffffu, s, o);
    int lane = tid & 31, warp = tid >> 5;
    if (lane == 0) ws[warp] = s;
    __syncthreads();
    if (tid < 8) {
        float v = ws[tid];
#pragma unroll
        for (int o = 4; o > 0; o >>= 1) v += __shfl_down_sync(0xffu, v, o);
        if (tid == 0) {
            out[OUT_EMB + N_ROWS]     = 0.25f * (float)(g_accum * (1.0 / 2097152.0));
            out[OUT_EMB + N_ROWS + 1] = expf(-v);
        }
    }
}

// ---------------- launch ----------------
extern "C" void kernel_launch(void* const* d_in, const int* in_sizes, int n_in,
                              void* d_out, int out_size) {
    const float* z = (const float*)d_in[0];
    const float* emb = (const float*)d_in[1];
    if (in_sizes[0] == K_CODES * C_DIM && in_sizes[1] == N_ROWS * C_DIM) {
        z = (const float*)d_in[1];
        emb = (const float*)d_in[0];
    }
    float* out = (float*)d_out;

    cudaFuncSetAttribute(vq_gemm, cudaFuncAttributeMaxDynamicSharedMemorySize,
                         SMEM_TOTAL);

    init_kernel<<<64, 256>>>();
    split_z<<<dim3(256, 8), dim3(32, 8)>>>(z);
    split_e<<<2048, 256>>>(emb);
    vq_gemm<<<dim3(64, 128), 256, SMEM_TOTAL>>>();
    merge_kernel<<<32, 256>>>();
    out_kernel<<<8192, 256>>>(z, emb, out);
    final_kernel<<<1, 256>>>(out);
}

// round 7
// speedup vs baseline: 1.0467x; 1.0467x over previous
#include <cuda_runtime.h>
#include <cuda_fp16.h>
#include <math.h>
#include <float.h>
#include <stdint.h>

#define N_ROWS   8192
#define C_DIM    256
#define K_CODES  16384
#define OUT_EMB  2097152
#define GRID_P   148
#define N_TILES  4096   // 64 m-tiles x 64 n-tiles

// ---------------- scratch (static, no allocations) ----------------
__device__ __align__(16) __half g_zhi[N_ROWS * C_DIM];
__device__ __align__(16) __half g_zlo[N_ROWS * C_DIM];
__device__ __align__(16) __half g_ehi[K_CODES * C_DIM];
__device__ __align__(16) __half g_elo[K_CODES * C_DIM];
__device__ __align__(16) float g_enorm[K_CODES];
__device__ unsigned long long g_best[N_ROWS];
__device__ int    g_idx[N_ROWS];
__device__ int    g_hist[K_CODES];
__device__ double g_accum;

// ---------------- PTX helpers (compute_100-legal) ----------------
__device__ __forceinline__ uint32_t smem_u32(const void* p) {
    uint32_t a;
    asm("{ .reg .u64 t; cvta.to.shared.u64 t, %1; cvt.u32.u64 %0, t; }"
        : "=r"(a) : "l"(p));
    return a;
}
__device__ __forceinline__ void cp_async16(uint32_t saddr, const void* gaddr) {
    asm volatile("cp.async.cg.shared.global [%0], [%1], 16;\n"
                 :: "r"(saddr), "l"(gaddr));
}
__device__ __forceinline__ void cp_commit() {
    asm volatile("cp.async.commit_group;\n");
}
template <int N>
__device__ __forceinline__ void cp_wait() {
    asm volatile("cp.async.wait_group %0;\n" :: "n"(N));
}
__device__ __forceinline__ void ldsm4(uint32_t* r, uint32_t addr) {
    asm volatile("ldmatrix.sync.aligned.m8n8.x4.shared.b16 {%0,%1,%2,%3}, [%4];"
                 : "=r"(r[0]), "=r"(r[1]), "=r"(r[2]), "=r"(r[3]) : "r"(addr));
}
__device__ __forceinline__ void mma_f16(float* d, const uint32_t* a,
                                        uint32_t b0, uint32_t b1) {
    asm volatile(
        "mma.sync.aligned.m16n8k16.row.col.f32.f16.f16.f32 "
        "{%0,%1,%2,%3}, {%4,%5,%6,%7}, {%8,%9}, {%0,%1,%2,%3};"
        : "+f"(d[0]), "+f"(d[1]), "+f"(d[2]), "+f"(d[3])
        : "r"(a[0]), "r"(a[1]), "r"(a[2]), "r"(a[3]), "r"(b0), "r"(b1));
}

// ---------------- init ----------------
__global__ void init_kernel() {
    int t = blockIdx.x * blockDim.x + threadIdx.x;
    if (t < K_CODES) g_hist[t] = 0;
    if (t < N_ROWS) g_best[t] = 0xFFFFFFFFFFFFFFFFull;
    if (t == 0) g_accum = 0.0;
}

// ---------------- z [B,C,T,H,W] -> zhi/zlo [N, C] (fp16 split) ------
__global__ void split_z(const float* __restrict__ z) {
    __shared__ float s[32][33];
    int n0 = blockIdx.x * 32, c0 = blockIdx.y * 32;
    int tx = threadIdx.x, ty = threadIdx.y;
#pragma unroll
    for (int k = 0; k < 4; k++) {
        int yy = ty + k * 8;
        int c = c0 + yy;
        int n = n0 + tx;
        int b = n >> 11, thw = n & 2047;
        s[yy][tx] = z[((b * C_DIM + c) << 11) + thw];
    }
    __syncthreads();
#pragma unroll
    for (int k = 0; k < 4; k++) {
        int yy = ty + k * 8;
        float v = s[tx][yy];
        __half hi = __float2half_rn(v);
        float lo = v - __half2float(hi);
        int o = (n0 + yy) * C_DIM + c0 + tx;
        g_zhi[o] = hi;
        g_zlo[o] = __float2half_rn(lo);
    }
}

// ---------------- emb -> ehi/elo (fp16 split) + ||e||^2 -------------
__global__ void split_e(const float* __restrict__ emb) {
    int w = (blockIdx.x * blockDim.x + threadIdx.x) >> 5;
    int lane = threadIdx.x & 31;
    if (w >= K_CODES) return;
    const float4* e4 = (const float4*)(emb + (size_t)w * C_DIM);
    __half2* h2 = (__half2*)(g_ehi + (size_t)w * C_DIM);
    __half2* l2 = (__half2*)(g_elo + (size_t)w * C_DIM);
    float s = 0.f;
#pragma unroll
    for (int q = 0; q < 2; q++) {
        float4 v = e4[q * 32 + lane];
        s += v.x * v.x + v.y * v.y + v.z * v.z + v.w * v.w;
        __half hx = __float2half_rn(v.x), hy = __float2half_rn(v.y);
        __half hz = __float2half_rn(v.z), hw = __float2half_rn(v.w);
        __half lx = __float2half_rn(v.x - __half2float(hx));
        __half ly = __float2half_rn(v.y - __half2float(hy));
        __half lz = __float2half_rn(v.z - __half2float(hz));
        __half lw = __float2half_rn(v.w - __half2float(hw));
        h2[(q * 32 + lane) * 2 + 0] = __halves2half2(hx, hy);
        h2[(q * 32 + lane) * 2 + 1] = __halves2half2(hz, hw);
        l2[(q * 32 + lane) * 2 + 0] = __halves2half2(lx, ly);
        l2[(q * 32 + lane) * 2 + 1] = __halves2half2(lz, lw);
    }
#pragma unroll
    for (int o = 16; o > 0; o >>= 1) s += __shfl_down_sync(0xffffffffu, s, o);
    if (lane == 0) g_enorm[w] = s;
}

// ---------------- persistent fused 3xFP16 GEMM + argmin -------------
// 148 persistent CTAs; tile 128(M) x 256(N); warp tile 64x64 (2x4 warps).
// Tile = 4 k-chunks of 64; cp.async double-buffer pipelined ACROSS tiles.
// stage: Ahi 16K | Alo 16K | Bhi 32K | Blo 32K = 96K; x2 = 192K.
#define STAGE_BYTES 98304
#define CTRL_OFF    196608
#define SMEM_TOTAL  (196608 + 4096)

__global__ void __launch_bounds__(256, 1)
vq_gemm() {
    extern __shared__ __align__(1024) char smem[];
    const uint32_t sb = smem_u32(smem);
    const int tid = threadIdx.x;
    const int wid = tid >> 5, l = tid & 31;
    const int warpM = wid >> 2, warpN = wid & 3;

    float* rv = (float*)(smem + CTRL_OFF);          // 2048 B
    int*   ri = (int*)(smem + CTRL_OFF + 2048);     // 2048 B

    // ldmatrix lane addressing (16-row tiles, two 16B k-segments)
    uint32_t aoff[4], boff[4];
    int a7[4], b7[4];
#pragma unroll
    for (int mt = 0; mt < 4; mt++) {
        int row = warpM * 64 + mt * 16 + ((l >> 3) & 1) * 8 + (l & 7);
        aoff[mt] = (uint32_t)(row * 128);
        a7[mt] = row & 7;
    }
#pragma unroll
    for (int ntp = 0; ntp < 4; ntp++) {
        int row = warpN * 64 + ntp * 16 + ((l >> 3) & 1) * 8 + (l & 7);
        boff[ntp] = (uint32_t)(row * 128);
        b7[ntp] = row & 7;
    }
    const int segbit = l >> 4;

    const int bid = blockIdx.x;
    const int cnt = (N_TILES - bid + GRID_P - 1) / GRID_P;  // my tile count
    const int P = cnt * 4;                                   // my chunk count

    // stream position p -> tile (bid + (p>>2)*GRID_P), k-chunk (p&3)
    auto load_pos = [&](int p) {
        const int t = bid + (p >> 2) * GRID_P;
        const int m0 = (t >> 6) << 7;
        const int n0 = (t & 63) << 8;
        const int k0 = (p & 3) * 64;
        const uint32_t base = sb + (p & 1) * STAGE_BYTES;
#pragma unroll
        for (int q = 0; q < 4; q++) {       // A: 128 rows x 128 B per array
            int idx = q * 256 + tid;
            int row = idx >> 3, seg = idx & 7;
            uint32_t so = (uint32_t)(row * 128 + ((seg ^ (row & 7)) << 4));
            size_t go = (size_t)(m0 + row) * C_DIM + k0 + seg * 8;
            cp_async16(base + so,         g_zhi + go);
            cp_async16(base + 16384 + so, g_zlo + go);
        }
#pragma unroll
        for (int q = 0; q < 8; q++) {       // B: 256 rows x 128 B per array
            int idx = q * 256 + tid;
            int row = idx >> 3, seg = idx & 7;
            uint32_t so = (uint32_t)(row * 128 + ((seg ^ (row & 7)) << 4));
            size_t go = (size_t)(n0 + row) * C_DIM + k0 + seg * 8;
            cp_async16(base + 32768 + so, g_ehi + go);
            cp_async16(base + 65536 + so, g_elo + go);
        }
        cp_commit();
    };

    float acc[4][8][4];
#pragma unroll
    for (int mt = 0; mt < 4; mt++)
#pragma unroll
        for (int nt = 0; nt < 8; nt++)
#pragma unroll
            for (int r = 0; r < 4; r++) acc[mt][nt][r] = 0.f;

    if (P > 0) load_pos(0);
    if (P > 1) load_pos(1);

    for (int p = 0; p < P; p++) {
        if (p + 1 < P) cp_wait<1>(); else cp_wait<0>();
        __syncthreads();
        const uint32_t base = sb + (p & 1) * STAGE_BYTES;

#pragma unroll
        for (int ks = 0; ks < 4; ks++) {            // k16 steps within chunk64
            const int seg = 2 * ks + segbit;
            uint32_t Ah[4][4], Al[4][4];
#pragma unroll
            for (int mt = 0; mt < 4; mt++) {
                uint32_t ad = base + aoff[mt] + (uint32_t)((seg ^ a7[mt]) << 4);
                ldsm4(Ah[mt], ad);
                ldsm4(Al[mt], ad + 16384);
            }
#pragma unroll
            for (int ntp = 0; ntp < 4; ntp++) {
                uint32_t Bh[4], Bl[4];
                uint32_t bd = base + 32768 + boff[ntp] +
                              (uint32_t)((seg ^ b7[ntp]) << 4);
                ldsm4(Bh, bd);
                ldsm4(Bl, bd + 32768);
#pragma unroll
                for (int sub = 0; sub < 2; sub++) {
                    int nt = ntp * 2 + sub;
#pragma unroll
                    for (int mt = 0; mt < 4; mt++) {
                        mma_f16(acc[mt][nt], Ah[mt], Bh[sub], Bh[sub + 2]);
                        mma_f16(acc[mt][nt], Ah[mt], Bl[sub], Bl[sub + 2]);
                        mma_f16(acc[mt][nt], Al[mt], Bh[sub], Bh[sub + 2]);
                    }
                }
            }
        }
        __syncthreads();
        if (p + 2 < P) load_pos(p + 2);

        if ((p & 3) == 3) {
            // ---- tile epilogue (next tile's loads already in flight) ----
            const int t = bid + (p >> 2) * GRID_P;
            const int m0 = (t >> 6) << 7;
            const int n0 = (t & 63) << 8;
#pragma unroll
            for (int s = 0; s < 8; s++) {
                const int mt = s >> 1, half = s & 1;
                const int rloc = warpM * 64 + mt * 16 + half * 8 + (l >> 2);
                float bv = INFINITY;
                int bi = 0;
#pragma unroll
                for (int nt = 0; nt < 8; nt++)
#pragma unroll
                    for (int j = 0; j < 2; j++) {
                        int cl = warpN * 64 + (nt >> 1) * 16 + (nt & 1) * 8 +
                                 2 * (l & 3) + j;
                        float d = __ldg(&g_enorm[n0 + cl]) -
                                  2.0f * acc[mt][nt][half * 2 + j];
                        if (d < bv) { bv = d; bi = n0 + cl; }
                        acc[mt][nt][half * 2 + j] = 0.f;   // reset for next tile
                    }
#pragma unroll
                for (int off = 1; off <= 2; off <<= 1) {
                    float ov = __shfl_xor_sync(0xffffffffu, bv, off);
                    int   oi = __shfl_xor_sync(0xffffffffu, bi, off);
                    if (ov < bv || (ov == bv && oi < bi)) { bv = ov; bi = oi; }
                }
                if ((l & 3) == 0) {
                    rv[warpN * 128 + rloc] = bv;
                    ri[warpN * 128 + rloc] = bi;
                }
            }
            __syncthreads();
            if (tid < 128) {
                float bv = rv[tid];
                int bi = ri[tid];
#pragma unroll
                for (int w = 1; w < 4; w++) {
                    float v = rv[w * 128 + tid];
                    int i2 = ri[w * 128 + tid];
                    if (v < bv || (v == bv && i2 < bi)) { bv = v; bi = i2; }
                }
                unsigned u = __float_as_uint(bv);
                u = (u & 0x80000000u) ? ~u : (u | 0x80000000u);
                unsigned long long key =
                    ((unsigned long long)u << 32) | (unsigned)bi;
                atomicMin(&g_best[m0 + tid], key);
            }
        }
    }
}

// ---------------- merge best -> idx + histogram ----------------
__global__ void merge_kernel() {
    int n = blockIdx.x * blockDim.x + threadIdx.x;
    if (n >= N_ROWS) return;
    int idx = (int)(g_best[n] & 0xFFFFFFFFull);
    g_idx[n] = idx;
    atomicAdd(&g_hist[idx], 1);
}

// ---------------- gather + channels-first output + loss ----------
__global__ void out_kernel(const float* __restrict__ z,
                           const float* __restrict__ emb,
                           float* __restrict__ out) {
    int i = blockIdx.x * blockDim.x + threadIdx.x;
    int b = i >> 19;
    int rem = i & 524287;
    int c = rem >> 11;
    int thw = rem & 2047;
    int n = (b << 11) | thw;
    int idx = g_idx[n];
    float e = emb[(size_t)idx * C_DIM + c];
    out[i] = e;
    if (c == 0) out[OUT_EMB + n] = (float)idx;
    float d = z[i] - e;
    float ss = d * d;
#pragma unroll
    for (int o = 16; o > 0; o >>= 1) ss += __shfl_down_sync(0xffffffffu, ss, o);
    __shared__ float ws[8];
    int lane = threadIdx.x & 31, warp = threadIdx.x >> 5;
    if (lane == 0) ws[warp] = ss;
    __syncthreads();
    if (threadIdx.x < 8) {
        float v = ws[threadIdx.x];
#pragma unroll
        for (int o = 4; o > 0; o >>= 1) v += __shfl_down_sync(0xffu, v, o);
        if (threadIdx.x == 0) atomicAdd(&g_accum, (double)v);
    }
}

// ---------------- perplexity + loss finalize ----------------
__global__ void final_kernel(float* __restrict__ out) {
    __shared__ float ws[8];
    int tid = threadIdx.x;
    float s = 0.f;
    for (int k = tid; k < K_CODES; k += 256) {
        float p = (float)g_hist[k] * (1.0f / N_ROWS);
        s += p * logf(p + 1e-10f);
    }
#pragma unroll
    for (int o = 16; o > 0; o >>= 1) s += __shfl_down_sync(0xffffffffu, s, o);
    int lane = tid & 31, warp = tid >> 5;
    if (lane == 0) ws[warp] = s;
    __syncthreads();
    if (tid < 8) {
        float v = ws[tid];
#pragma unroll
        for (int o = 4; o > 0; o >>= 1) v += __shfl_down_sync(0xffu, v, o);
        if (tid == 0) {
            out[OUT_EMB + N_ROWS]     = 0.25f * (float)(g_accum * (1.0 / 2097152.0));
            out[OUT_EMB + N_ROWS + 1] = expf(-v);
        }
    }
}

// ---------------- launch ----------------
extern "C" void kernel_launch(void* const* d_in, const int* in_sizes, int n_in,
                              void* d_out, int out_size) {
    const float* z = (const float*)d_in[0];
    const float* emb = (const float*)d_in[1];
    if (in_sizes[0] == K_CODES * C_DIM && in_sizes[1] == N_ROWS * C_DIM) {
        z = (const float*)d_in[1];
        emb = (const float*)d_in[0];
    }
    float* out = (float*)d_out;

    cudaFuncSetAttribute(vq_gemm, cudaFuncAttributeMaxDynamicSharedMemorySize,
                         SMEM_TOTAL);

    init_kernel<<<64, 256>>>();
    split_z<<<dim3(256, 8), dim3(32, 8)>>>(z);
    split_e<<<2048, 256>>>(emb);
    vq_gemm<<<GRID_P, 256, SMEM_TOTAL>>>();
    merge_kernel<<<32, 256>>>();
    out_kernel<<<8192, 256>>>(z, emb, out);
    final_kernel<<<1, 256>>>(out);
}